// round 7
// baseline (speedup 1.0000x reference)
#include <cuda_runtime.h>
#include <math.h>

#define BB 16384
#define SS 16
#define NSTEPS 50
#define LATENT 128
#define HID 64
#define DTC 0.02f
#define SQRT_DT 0.14142135623730951f
#define LOG2E 1.4426950408889634f
#define LN2 0.6931471805599453f
#define EXPM50 1.9287498479639178e-22f /* exp(-50) */

typedef unsigned long long u64t;

// Scratch (no cudaMalloc allowed)
__device__ float g_zc[BB * HID];   // per-b hidden bias: z@W1[:,2:].T + b1
__device__ float g_halfb[BB];      // 0.5*boundary
__device__ float g_ndt[BB];        // non-decision time

__device__ __forceinline__ float ex2f(float v) {
    float r; asm("ex2.approx.f32 %0, %1;" : "=f"(r) : "f"(v)); return r;
}
__device__ __forceinline__ float lg2f(float v) {
    float r; asm("lg2.approx.f32 %0, %1;" : "=f"(r) : "f"(v)); return r;
}
__device__ __forceinline__ float tanhapx(float v) {
    float r; asm("tanh.approx.f32 %0, %1;" : "=f"(r) : "f"(v)); return r;
}
__device__ __forceinline__ u64t pack2(float lo, float hi) {
    u64t r;
    asm("mov.b64 %0, {%1, %2};" : "=l"(r)
        : "r"(__float_as_uint(lo)), "r"(__float_as_uint(hi)));
    return r;
}
__device__ __forceinline__ void unpack2(u64t v, float& lo, float& hi) {
    unsigned a, b;
    asm("mov.b64 {%0, %1}, %2;" : "=r"(a), "=r"(b) : "l"(v));
    lo = __uint_as_float(a); hi = __uint_as_float(b);
}
__device__ __forceinline__ u64t fma2(u64t a, u64t b, u64t c) {
    u64t r; asm("fma.rn.f32x2 %0, %1, %2, %3;" : "=l"(r) : "l"(a), "l"(b), "l"(c));
    return r;
}
__device__ __forceinline__ float fix_out(float v) {
    if (isnan(v)) return 0.0f;
    return fminf(fmaxf(v, -3.402823466e38f), 3.402823466e38f);
}

// ---------------------------------------------------------------------------
// Precompute: zc[b][j] = b1[j] + sum_k z[b,k]*W1[j,2+k]; boundary & ndt per b.
// ---------------------------------------------------------------------------
__global__ __launch_bounds__(256) void precompute_kernel(
    const float* __restrict__ z,  const float* __restrict__ W1,
    const float* __restrict__ b1, const float* __restrict__ Wb,
    const float* __restrict__ bbv, const float* __restrict__ Wn,
    const float* __restrict__ bnv)
{
    __shared__ __align__(16) float sW[HID * 130];   // whole W1, 33.3KB
    __shared__ __align__(16) float sz[16 * LATENT]; // 16 z rows, 8KB
    const int tid = threadIdx.x;
    const int b0 = blockIdx.x * 16;

    for (int i = tid; i < HID * 130; i += 256) sW[i] = W1[i];
    for (int i = tid; i < 16 * LATENT; i += 256) sz[i] = z[b0 * LATENT + i];
    __syncthreads();

    const int j = tid & 63;
    const int bg = tid >> 6;   // 0..3, each handles 4 b's
    const float* wrow = sW + j * 130 + 2;
    float a0, a1, a2, a3;
    a0 = a1 = a2 = a3 = b1[j];
    const float* z0 = sz + (bg * 4 + 0) * LATENT;
    const float* z1 = sz + (bg * 4 + 1) * LATENT;
    const float* z2 = sz + (bg * 4 + 2) * LATENT;
    const float* z3 = sz + (bg * 4 + 3) * LATENT;
    #pragma unroll 8
    for (int k = 0; k < LATENT; k += 4) {
        float w0 = wrow[k], w1 = wrow[k + 1], w2 = wrow[k + 2], w3 = wrow[k + 3];
        float4 q0 = *(const float4*)(z0 + k);
        float4 q1 = *(const float4*)(z1 + k);
        float4 q2 = *(const float4*)(z2 + k);
        float4 q3 = *(const float4*)(z3 + k);
        a0 = fmaf(w0, q0.x, a0); a0 = fmaf(w1, q0.y, a0); a0 = fmaf(w2, q0.z, a0); a0 = fmaf(w3, q0.w, a0);
        a1 = fmaf(w0, q1.x, a1); a1 = fmaf(w1, q1.y, a1); a1 = fmaf(w2, q1.z, a1); a1 = fmaf(w3, q1.w, a1);
        a2 = fmaf(w0, q2.x, a2); a2 = fmaf(w1, q2.y, a2); a2 = fmaf(w2, q2.z, a2); a2 = fmaf(w3, q2.w, a2);
        a3 = fmaf(w0, q3.x, a3); a3 = fmaf(w1, q3.y, a3); a3 = fmaf(w2, q3.z, a3); a3 = fmaf(w3, q3.w, a3);
    }
    g_zc[(b0 + bg * 4 + 0) * HID + j] = a0;
    g_zc[(b0 + bg * 4 + 1) * HID + j] = a1;
    g_zc[(b0 + bg * 4 + 2) * HID + j] = a2;
    g_zc[(b0 + bg * 4 + 3) * HID + j] = a3;

    if (tid < 32) {
        const int bl = tid >> 1;
        const int isn = tid & 1;
        const float* wv = isn ? Wn : Wb;
        const float* zz = sz + bl * LATENT;
        float acc = isn ? bnv[0] : bbv[0];
        #pragma unroll 8
        for (int k = 0; k < LATENT; k++) acc = fmaf(wv[k], zz[k], acc);
        float sp = fmaxf(acc, 0.0f) + log1pf(expf(-fabsf(acc)));
        if (isn) g_ndt[b0 + bl] = sp + 0.05f;
        else     g_halfb[b0 + bl] = 0.5f * (sp + 0.3f);
    }
}

// ---------------------------------------------------------------------------
// Main SDE kernel. One warp per b. Lane = (rep 0..3) x (sim-pair 0..7).
// Every lane evaluates its 16 hidden units (8 f32x2 pairs, weights in
// REGISTERS) for BOTH sims of its pair, but owns the survival state of only
// ONE chain: reps {0,1} -> chain A (sim sp), reps {2,3} -> chain B (sim sp+8).
// The second reduction round is an exchange, so the tail (softplus + hazard,
// 3 MUFU) is executed once per chain instead of duplicated 4x.
// Block 128 = 4 b's.
// ---------------------------------------------------------------------------
__global__ __launch_bounds__(128, 4) void sde_kernel(
    const float* __restrict__ W1, const float* __restrict__ W2,
    const float* __restrict__ b2, const float* __restrict__ noise,
    const float* __restrict__ osc, const float* __restrict__ obi,
    float* __restrict__ out)
{
    const int tid = threadIdx.x;
    const int lane = tid & 31;
    const int rep = lane & 3;         // which 16-unit slice
    const int sp  = lane >> 2;        // sim pair: sims sp and sp+8
    const int w   = tid >> 5;         // warp 0..3
    const int b   = blockIdx.x * 4 + w;
    const int jbase = rep * 16;
    const bool isA = (rep < 2);

    u64t w1x2[8], w1t2[8], zc2[8], w2a2[8], w2b2[8];
    #pragma unroll
    for (int p = 0; p < 8; p++) {
        const int j = jbase + p * 2;
        w1x2[p] = pack2(W1[j * 130],       W1[(j + 1) * 130]);
        w1t2[p] = pack2(W1[j * 130 + 1],   W1[(j + 1) * 130 + 1]);
        zc2[p]  = pack2(g_zc[b * HID + j], g_zc[b * HID + j + 1]);
        w2a2[p] = pack2(W2[j],             W2[j + 1]);
        w2b2[p] = pack2(W2[HID + j],       W2[HID + j + 1]);
    }
    const float b2x = b2[0], b2y = b2[1];
    const float half_b = g_halfb[b];

    // shared x's (all lanes), private survival state (my chain only)
    float xA = 0.0f, xB = 0.0f;
    float p_my = 1.0f, rt_my = 0.0f, cr_my = 0.0f;
    const int nidx = b * SS + sp + (isA ? 0 : 8);
    float nz_my = noise[nidx];
    const int lbase = lane & 28;      // base lane of this sim-pair group

    #pragma unroll 1
    for (int k = 0; k < NSTEPS; k++) {
        const int k1 = (k + 1 < NSTEPS) ? (k + 1) : (NSTEPS - 1);
        const float nz_next = noise[k1 * (BB * SS) + nidx];
        const float tk = (float)k * DTC;
        const u64t tk2 = pack2(tk, tk);
        const u64t xA2 = pack2(xA, xA);
        const u64t xB2 = pack2(xB, xB);

        u64t daA = 0ull, dbA = 0ull, daB = 0ull, dbB = 0ull;
        #pragma unroll
        for (int p = 0; p < 8; p++) {
            const u64t base = fma2(tk2, w1t2[p], zc2[p]);   // shared A/B
            const u64t uA = fma2(xA2, w1x2[p], base);
            const u64t uB = fma2(xB2, w1x2[p], base);
            float al, ah, bl2, bh;
            unpack2(uA, al, ah);
            unpack2(uB, bl2, bh);
            const u64t hA = pack2(tanhapx(al), tanhapx(ah));
            const u64t hB = pack2(tanhapx(bl2), tanhapx(bh));
            daA = fma2(hA, w2a2[p], daA);
            dbA = fma2(hA, w2b2[p], dbA);
            daB = fma2(hB, w2a2[p], daB);
            dbB = fma2(hB, w2b2[p], dbB);
        }
        float t0, t1;
        unpack2(daA, t0, t1); float pdA = t0 + t1;
        unpack2(dbA, t0, t1); float pfA = t0 + t1;
        unpack2(daB, t0, t1); float pdB = t0 + t1;
        unpack2(dbB, t0, t1); float pfB = t0 + t1;
        // round 1: reduce within rep pairs {0,1} and {2,3}
        pdA += __shfl_xor_sync(0xffffffffu, pdA, 1);
        pfA += __shfl_xor_sync(0xffffffffu, pfA, 1);
        pdB += __shfl_xor_sync(0xffffffffu, pdB, 1);
        pfB += __shfl_xor_sync(0xffffffffu, pfB, 1);
        // round 2: exchange — reps {0,1} end with chain A totals, {2,3} with B
        const float upd = isA ? pdB : pdA;
        const float upf = isA ? pfB : pfA;
        const float vpd = __shfl_xor_sync(0xffffffffu, upd, 2);
        const float vpf = __shfl_xor_sync(0xffffffffu, upf, 2);
        const float pd = (isA ? pdA : pdB) + vpd;
        const float pf = (isA ? pfA : pfB) + vpf;

        // --- tail for MY chain only (3 MUFU) ---
        const float dyn0 = pd + b2x;
        const float dyn1 = pf + b2y;
        const float drift = fminf(fmaxf(dyn0, -5.0f), 5.0f);
        const float e1 = ex2f(-fabsf(dyn1) * LOG2E);
        const float spv = fmaxf(dyn1, 0.0f) + lg2f(1.0f + e1) * LN2;
        const float diff = spv + 0.1f;
        float x_my = isA ? xA : xB;
        x_my = fmaf(diff * SQRT_DT, nz_my, fmaf(drift, DTC, x_my));
        x_my = fminf(fmaxf(x_my, -10.0f), 10.0f);
        const float dist = fabsf(x_my) - half_b;
        const float sg = fmaf(0.5f, tanhapx(10.0f * dist), 0.5f);
        const float hz = fminf(fmaxf(sg, 0.0f), 0.99f);
        const float sb = fmaxf(p_my, EXPM50);
        const float cp = sb * hz;
        p_my = p_my * (1.0f - hz);
        rt_my = fmaf(cp, tk + DTC, rt_my);
        cr_my += (x_my > 0.0f) ? cp : 0.0f;

        // broadcast updated x's back to all reps of this sim-pair group
        xA = __shfl_sync(0xffffffffu, x_my, lbase + 0);
        xB = __shfl_sync(0xffffffffu, x_my, lbase + 2);

        nz_my = nz_next;
    }

    const float rem = fmaxf(p_my, EXPM50);
    rt_my = fmaf(rem, (float)NSTEPS * DTC, rt_my);
    cr_my = fmaf(rem, 0.5f, cr_my);
    const float rtms = (rt_my + g_ndt[b]) * 1000.0f;

    // per-b reduction over the 16 sims: rep 0 publishes chain A (sim sp),
    // rep 2 publishes chain B (sim sp+8)
    __shared__ float s_rt[4][16];
    __shared__ float s_cr[4][16];
    if (rep == 0) { s_rt[w][sp]     = rtms; s_cr[w][sp]     = cr_my; }
    if (rep == 2) { s_rt[w][sp + 8] = rtms; s_cr[w][sp + 8] = cr_my; }
    __syncthreads();

    if (tid < 4) {
        float m = 0.0f, c = 0.0f;
        #pragma unroll
        for (int i = 0; i < 16; i++) { m += s_rt[tid][i]; c += s_cr[tid][i]; }
        m *= (1.0f / 16.0f);
        c *= (1.0f / 16.0f);
        float v = 0.0f;
        #pragma unroll
        for (int i = 0; i < 16; i++) {
            float d = s_rt[tid][i] - m;
            v = fmaf(d, d, v);
        }
        const float sd = sqrtf(v * (1.0f / 15.0f));  // ddof=1
        const int bo = blockIdx.x * 4 + tid;
        const float o0 = m * osc[0] + obi[0];
        const float o1 = (sd + 0.001f) * osc[1] + obi[1];
        const float o2 = c * osc[2] + obi[2];
        out[bo * 3 + 0] = fix_out(o0);
        out[bo * 3 + 1] = fix_out(o1);
        out[bo * 3 + 2] = fix_out(o2);
    }
}

extern "C" void kernel_launch(void* const* d_in, const int* in_sizes, int n_in,
                              void* d_out, int out_size)
{
    const float* z   = (const float*)d_in[0];
    const float* W1  = (const float*)d_in[1];
    const float* b1  = (const float*)d_in[2];
    const float* W2  = (const float*)d_in[3];
    const float* b2  = (const float*)d_in[4];
    const float* Wb  = (const float*)d_in[5];
    const float* bbv = (const float*)d_in[6];
    const float* Wn  = (const float*)d_in[7];
    const float* bnv = (const float*)d_in[8];
    const float* osc = (const float*)d_in[9];
    const float* obi = (const float*)d_in[10];
    const float* noise = (const float*)d_in[11];
    float* out = (float*)d_out;

    precompute_kernel<<<BB / 16, 256>>>(z, W1, b1, Wb, bbv, Wn, bnv);
    sde_kernel<<<BB / 4, 128>>>(W1, W2, b2, noise, osc, obi, out);
}

// round 8
// speedup vs baseline: 1.3515x; 1.3515x over previous
#include <cuda_runtime.h>
#include <cuda_fp16.h>
#include <math.h>

#define BB 16384
#define SS 16
#define NSTEPS 50
#define LATENT 128
#define HID 64
#define DTC 0.02f
#define SQRT_DT 0.14142135623730951f
#define LOG2E 1.4426950408889634f
#define LN2 0.6931471805599453f
#define EXPM50 1.9287498479639178e-22f /* exp(-50) */

typedef unsigned long long u64t;

// Scratch (no cudaMalloc allowed)
__device__ float g_zc[BB * HID];   // per-b hidden bias: z@W1[:,2:].T + b1
__device__ float g_halfb[BB];      // 0.5*boundary
__device__ float g_ndt[BB];        // non-decision time

__device__ __forceinline__ float ex2f(float v) {
    float r; asm("ex2.approx.f32 %0, %1;" : "=f"(r) : "f"(v)); return r;
}
__device__ __forceinline__ float lg2f(float v) {
    float r; asm("lg2.approx.f32 %0, %1;" : "=f"(r) : "f"(v)); return r;
}
__device__ __forceinline__ float tanhapx(float v) {
    float r; asm("tanh.approx.f32 %0, %1;" : "=f"(r) : "f"(v)); return r;
}
__device__ __forceinline__ half2 tanh2h(half2 x) {
    unsigned xi = *reinterpret_cast<unsigned*>(&x);
    unsigned r;
    asm("tanh.approx.f16x2 %0, %1;" : "=r"(r) : "r"(xi));
    return *reinterpret_cast<half2*>(&r);
}
__device__ __forceinline__ u64t pack2(float lo, float hi) {
    u64t r;
    asm("mov.b64 %0, {%1, %2};" : "=l"(r)
        : "r"(__float_as_uint(lo)), "r"(__float_as_uint(hi)));
    return r;
}
__device__ __forceinline__ void unpack2(u64t v, float& lo, float& hi) {
    unsigned a, b;
    asm("mov.b64 {%0, %1}, %2;" : "=r"(a), "=r"(b) : "l"(v));
    lo = __uint_as_float(a); hi = __uint_as_float(b);
}
__device__ __forceinline__ u64t fma2(u64t a, u64t b, u64t c) {
    u64t r; asm("fma.rn.f32x2 %0, %1, %2, %3;" : "=l"(r) : "l"(a), "l"(b), "l"(c));
    return r;
}
// Sum the two f16 halves of v as f32, using ALU-pipe bit-expansion
// (exact for normal f16; subnormals introduce <= 6.1e-5 abs error).
__device__ __forceinline__ float h2sum(half2 v) {
    unsigned r = *reinterpret_cast<unsigned*>(&v);
    unsigned lo = ((r << 16) & 0x80000000u) | (((r & 0x7FFFu) << 13) + 0x38000000u);
    unsigned hi = (r & 0x80000000u) | (((r >> 3) & 0x0FFFE000u) + 0x38000000u);
    return __uint_as_float(lo) + __uint_as_float(hi);
}
__device__ __forceinline__ float fix_out(float v) {
    if (isnan(v)) return 0.0f;
    return fminf(fmaxf(v, -3.402823466e38f), 3.402823466e38f);
}

// ---------------------------------------------------------------------------
// Precompute: zc[b][j] = b1[j] + sum_k z[b,k]*W1[j,2+k]; boundary & ndt per b.
// ---------------------------------------------------------------------------
__global__ __launch_bounds__(256) void precompute_kernel(
    const float* __restrict__ z,  const float* __restrict__ W1,
    const float* __restrict__ b1, const float* __restrict__ Wb,
    const float* __restrict__ bbv, const float* __restrict__ Wn,
    const float* __restrict__ bnv)
{
    __shared__ __align__(16) float sW[HID * 130];   // whole W1, 33.3KB
    __shared__ __align__(16) float sz[16 * LATENT]; // 16 z rows, 8KB
    const int tid = threadIdx.x;
    const int b0 = blockIdx.x * 16;

    for (int i = tid; i < HID * 130; i += 256) sW[i] = W1[i];
    for (int i = tid; i < 16 * LATENT; i += 256) sz[i] = z[b0 * LATENT + i];
    __syncthreads();

    const int j = tid & 63;
    const int bg = tid >> 6;   // 0..3, each handles 4 b's
    const float* wrow = sW + j * 130 + 2;
    float a0, a1, a2, a3;
    a0 = a1 = a2 = a3 = b1[j];
    const float* z0 = sz + (bg * 4 + 0) * LATENT;
    const float* z1 = sz + (bg * 4 + 1) * LATENT;
    const float* z2 = sz + (bg * 4 + 2) * LATENT;
    const float* z3 = sz + (bg * 4 + 3) * LATENT;
    #pragma unroll 8
    for (int k = 0; k < LATENT; k += 4) {
        float w0 = wrow[k], w1 = wrow[k + 1], w2 = wrow[k + 2], w3 = wrow[k + 3];
        float4 q0 = *(const float4*)(z0 + k);
        float4 q1 = *(const float4*)(z1 + k);
        float4 q2 = *(const float4*)(z2 + k);
        float4 q3 = *(const float4*)(z3 + k);
        a0 = fmaf(w0, q0.x, a0); a0 = fmaf(w1, q0.y, a0); a0 = fmaf(w2, q0.z, a0); a0 = fmaf(w3, q0.w, a0);
        a1 = fmaf(w0, q1.x, a1); a1 = fmaf(w1, q1.y, a1); a1 = fmaf(w2, q1.z, a1); a1 = fmaf(w3, q1.w, a1);
        a2 = fmaf(w0, q2.x, a2); a2 = fmaf(w1, q2.y, a2); a2 = fmaf(w2, q2.z, a2); a2 = fmaf(w3, q2.w, a2);
        a3 = fmaf(w0, q3.x, a3); a3 = fmaf(w1, q3.y, a3); a3 = fmaf(w2, q3.z, a3); a3 = fmaf(w3, q3.w, a3);
    }
    g_zc[(b0 + bg * 4 + 0) * HID + j] = a0;
    g_zc[(b0 + bg * 4 + 1) * HID + j] = a1;
    g_zc[(b0 + bg * 4 + 2) * HID + j] = a2;
    g_zc[(b0 + bg * 4 + 3) * HID + j] = a3;

    if (tid < 32) {
        const int bl = tid >> 1;
        const int isn = tid & 1;
        const float* wv = isn ? Wn : Wb;
        const float* zz = sz + bl * LATENT;
        float acc = isn ? bnv[0] : bbv[0];
        #pragma unroll 8
        for (int k = 0; k < LATENT; k++) acc = fmaf(wv[k], zz[k], acc);
        float sp = fmaxf(acc, 0.0f) + log1pf(expf(-fabsf(acc)));
        if (isn) g_ndt[b0 + bl] = sp + 0.05f;
        else     g_halfb[b0 + bl] = 0.5f * (sp + 0.3f);
    }
}

// ---------------------------------------------------------------------------
// Main SDE kernel. One warp per b. Lane = (rep 0..3) x (sim-pair 0..7);
// each lane runs TWO independent sims (sp, sp+8) sharing weight registers.
// Inner layer: u in f32 (fma.f32x2), pack to f16x2 (F2FP, fma pipe),
// tanh.approx.f16x2 (1 MUFU per 2 units), accumulate in f16 via HFMA2
// (fma pipe), final widening via ALU bit-trick — no XU-pipe F2F at all.
// Block 128 = 4 b's.
// ---------------------------------------------------------------------------
__global__ __launch_bounds__(128, 3) void sde_kernel(
    const float* __restrict__ W1, const float* __restrict__ W2,
    const float* __restrict__ b2, const float* __restrict__ noise,
    const float* __restrict__ osc, const float* __restrict__ obi,
    float* __restrict__ out)
{
    const int tid = threadIdx.x;
    const int lane = tid & 31;
    const int rep = lane & 3;         // which 16-unit slice
    const int sp  = lane >> 2;        // sim pair: sims sp and sp+8
    const int bl  = tid >> 5;         // 0..3
    const int b   = blockIdx.x * 4 + bl;
    const int jbase = rep * 16;

    u64t w1x2[8], w1t2[8], zc2[8];
    half2 w2a2[8], w2b2[8];
    #pragma unroll
    for (int p = 0; p < 8; p++) {
        const int j = jbase + p * 2;
        w1x2[p] = pack2(W1[j * 130],       W1[(j + 1) * 130]);
        w1t2[p] = pack2(W1[j * 130 + 1],   W1[(j + 1) * 130 + 1]);
        zc2[p]  = pack2(g_zc[b * HID + j], g_zc[b * HID + j + 1]);
        w2a2[p] = __floats2half2_rn(W2[j],       W2[j + 1]);
        w2b2[p] = __floats2half2_rn(W2[HID + j], W2[HID + j + 1]);
    }
    const float b2x = b2[0], b2y = b2[1];
    const float half_b = g_halfb[b];
    const half2 hzero = __floats2half2_rn(0.0f, 0.0f);

    float xA = 0.0f, pA = 1.0f, rtA = 0.0f, crA = 0.0f;
    float xB = 0.0f, pB = 1.0f, rtB = 0.0f, crB = 0.0f;
    const int nidxA = b * SS + sp;
    const int nidxB = nidxA + 8;
    float nzA = noise[nidxA];
    float nzB = noise[nidxB];

    #pragma unroll 1
    for (int k = 0; k < NSTEPS; k++) {
        const int k1 = (k + 1 < NSTEPS) ? (k + 1) : (NSTEPS - 1);
        const float nzA_n = noise[k1 * (BB * SS) + nidxA];
        const float nzB_n = noise[k1 * (BB * SS) + nidxB];
        const float tk = (float)k * DTC;
        const u64t tk2 = pack2(tk, tk);
        const u64t xA2 = pack2(xA, xA);
        const u64t xB2 = pack2(xB, xB);

        half2 daA = hzero, dbA = hzero, daB = hzero, dbB = hzero;
        #pragma unroll
        for (int p = 0; p < 8; p++) {
            const u64t base = fma2(tk2, w1t2[p], zc2[p]);   // shared A/B
            const u64t uA = fma2(xA2, w1x2[p], base);
            const u64t uB = fma2(xB2, w1x2[p], base);
            float al, ah, bl2, bh;
            unpack2(uA, al, ah);
            unpack2(uB, bl2, bh);
            const half2 hA = tanh2h(__floats2half2_rn(al, ah));
            const half2 hB = tanh2h(__floats2half2_rn(bl2, bh));
            daA = __hfma2(hA, w2a2[p], daA);
            dbA = __hfma2(hA, w2b2[p], dbA);
            daB = __hfma2(hB, w2a2[p], daB);
            dbB = __hfma2(hB, w2b2[p], dbB);
        }
        float pdA = h2sum(daA);
        float pfA = h2sum(dbA);
        float pdB = h2sum(daB);
        float pfB = h2sum(dbB);
        pdA += __shfl_xor_sync(0xffffffffu, pdA, 1);
        pfA += __shfl_xor_sync(0xffffffffu, pfA, 1);
        pdB += __shfl_xor_sync(0xffffffffu, pdB, 1);
        pfB += __shfl_xor_sync(0xffffffffu, pfB, 1);
        pdA += __shfl_xor_sync(0xffffffffu, pdA, 2);
        pfA += __shfl_xor_sync(0xffffffffu, pfA, 2);
        pdB += __shfl_xor_sync(0xffffffffu, pdB, 2);
        pfB += __shfl_xor_sync(0xffffffffu, pfB, 2);

        // --- tail, sim A ---
        {
            const float dyn0 = pdA + b2x;
            const float dyn1 = pfA + b2y;
            const float drift = fminf(fmaxf(dyn0, -5.0f), 5.0f);
            const float e1 = ex2f(-fabsf(dyn1) * LOG2E);
            const float spv = fmaxf(dyn1, 0.0f) + lg2f(1.0f + e1) * LN2;
            const float diff = spv + 0.1f;
            xA = fmaf(diff * SQRT_DT, nzA, fmaf(drift, DTC, xA));
            xA = fminf(fmaxf(xA, -10.0f), 10.0f);
            const float dist = fabsf(xA) - half_b;
            const float sg = fmaf(0.5f, tanhapx(10.0f * dist), 0.5f);
            const float hz = fminf(fmaxf(sg, 0.0f), 0.99f);
            const float sb = fmaxf(pA, EXPM50);
            const float cp = sb * hz;
            pA = pA * (1.0f - hz);
            rtA = fmaf(cp, tk + DTC, rtA);
            crA += (xA > 0.0f) ? cp : 0.0f;
        }
        // --- tail, sim B ---
        {
            const float dyn0 = pdB + b2x;
            const float dyn1 = pfB + b2y;
            const float drift = fminf(fmaxf(dyn0, -5.0f), 5.0f);
            const float e1 = ex2f(-fabsf(dyn1) * LOG2E);
            const float spv = fmaxf(dyn1, 0.0f) + lg2f(1.0f + e1) * LN2;
            const float diff = spv + 0.1f;
            xB = fmaf(diff * SQRT_DT, nzB, fmaf(drift, DTC, xB));
            xB = fminf(fmaxf(xB, -10.0f), 10.0f);
            const float dist = fabsf(xB) - half_b;
            const float sg = fmaf(0.5f, tanhapx(10.0f * dist), 0.5f);
            const float hz = fminf(fmaxf(sg, 0.0f), 0.99f);
            const float sb = fmaxf(pB, EXPM50);
            const float cp = sb * hz;
            pB = pB * (1.0f - hz);
            rtB = fmaf(cp, tk + DTC, rtB);
            crB += (xB > 0.0f) ? cp : 0.0f;
        }

        nzA = nzA_n;
        nzB = nzB_n;
    }

    const float remA = fmaxf(pA, EXPM50);
    const float remB = fmaxf(pB, EXPM50);
    rtA = fmaf(remA, (float)NSTEPS * DTC, rtA);
    rtB = fmaf(remB, (float)NSTEPS * DTC, rtB);
    crA = fmaf(remA, 0.5f, crA);
    crB = fmaf(remB, 0.5f, crB);
    const float ndt = g_ndt[b];
    const float rtmsA = (rtA + ndt) * 1000.0f;
    const float rtmsB = (rtB + ndt) * 1000.0f;

    // per-b reduction over the 16 sims
    __shared__ float s_rt[4][16];
    __shared__ float s_cr[4][16];
    if (rep == 0) {
        s_rt[bl][sp]     = rtmsA;  s_cr[bl][sp]     = crA;
        s_rt[bl][sp + 8] = rtmsB;  s_cr[bl][sp + 8] = crB;
    }
    __syncthreads();

    if (tid < 4) {
        float m = 0.0f, c = 0.0f;
        #pragma unroll
        for (int i = 0; i < 16; i++) { m += s_rt[tid][i]; c += s_cr[tid][i]; }
        m *= (1.0f / 16.0f);
        c *= (1.0f / 16.0f);
        float v = 0.0f;
        #pragma unroll
        for (int i = 0; i < 16; i++) {
            float d = s_rt[tid][i] - m;
            v = fmaf(d, d, v);
        }
        const float sd = sqrtf(v * (1.0f / 15.0f));  // ddof=1
        const int bo = blockIdx.x * 4 + tid;
        const float o0 = m * osc[0] + obi[0];
        const float o1 = (sd + 0.001f) * osc[1] + obi[1];
        const float o2 = c * osc[2] + obi[2];
        out[bo * 3 + 0] = fix_out(o0);
        out[bo * 3 + 1] = fix_out(o1);
        out[bo * 3 + 2] = fix_out(o2);
    }
}

extern "C" void kernel_launch(void* const* d_in, const int* in_sizes, int n_in,
                              void* d_out, int out_size)
{
    const float* z   = (const float*)d_in[0];
    const float* W1  = (const float*)d_in[1];
    const float* b1  = (const float*)d_in[2];
    const float* W2  = (const float*)d_in[3];
    const float* b2  = (const float*)d_in[4];
    const float* Wb  = (const float*)d_in[5];
    const float* bbv = (const float*)d_in[6];
    const float* Wn  = (const float*)d_in[7];
    const float* bnv = (const float*)d_in[8];
    const float* osc = (const float*)d_in[9];
    const float* obi = (const float*)d_in[10];
    const float* noise = (const float*)d_in[11];
    float* out = (float*)d_out;

    precompute_kernel<<<BB / 16, 256>>>(z, W1, b1, Wb, bbv, Wn, bnv);
    sde_kernel<<<BB / 4, 128>>>(W1, W2, b2, noise, osc, obi, out);
}